// round 4
// baseline (speedup 1.0000x reference)
#include <cuda_runtime.h>
#include <math.h>

// Shapes (fixed by the problem)
#define TDIM 4096
#define MDIM 512
#define DDIM 64
#define CDIM 64
#define WPAD 68            // padded row stride (floats) -> conflict-free float4 LDS
#define TILE 32            // rows (t values) per block
#define NTHR 256           // 8 warps, 4 rows per warp
#define LN_M 6.2383246250395075f   // ln(512)

// Scratch for cross-block reductions (no cudaMalloc allowed)
__device__ float g_avg[MDIM];
__device__ float g_kl;

static __device__ __forceinline__ float warp_sum(float v) {
#pragma unroll
    for (int m = 16; m > 0; m >>= 1) v += __shfl_xor_sync(0xffffffffu, v, m);
    return v;
}
static __device__ __forceinline__ float warp_max(float v) {
#pragma unroll
    for (int m = 16; m > 0; m >>= 1) v = fmaxf(v, __shfl_xor_sync(0xffffffffu, v, m));
    return v;
}

// Reduce v[8] (per-lane partials for 8 output columns) across 32 lanes.
// On return every lane holds the total for column c = (lane>>2)&7
// (each group of 4 lanes with equal bits[2:4] holds the same value).
static __device__ __forceinline__ float reduce8(float v[8], int lane) {
    {
        const bool hi = (lane & 16) != 0;
#pragma unroll
        for (int i = 0; i < 4; i++) {
            float send = hi ? v[i] : v[i + 4];
            float recv = __shfl_xor_sync(0xffffffffu, send, 16);
            v[i] = (hi ? v[i + 4] : v[i]) + recv;
        }
    }
    {
        const bool hi = (lane & 8) != 0;
#pragma unroll
        for (int i = 0; i < 2; i++) {
            float send = hi ? v[i] : v[i + 2];
            float recv = __shfl_xor_sync(0xffffffffu, send, 8);
            v[i] = (hi ? v[i + 2] : v[i]) + recv;
        }
    }
    {
        const bool hi = (lane & 4) != 0;
        float send = hi ? v[0] : v[1];
        float recv = __shfl_xor_sync(0xffffffffu, send, 4);
        v[0] = (hi ? v[1] : v[0]) + recv;
    }
    v[0] += __shfl_xor_sync(0xffffffffu, v[0], 2);
    v[0] += __shfl_xor_sync(0xffffffffu, v[0], 1);
    return v[0];
}

__global__ void vq_zero_kernel() {
    if (threadIdx.x < MDIM) g_avg[threadIdx.x] = 0.f;
    if (threadIdx.x == 0) g_kl = 0.f;
}

// Shared layout (floats):
//   w2  [512][68]  staged weight (padded)
//   xs  [32][68]   2*x tile, row-major (padded)
//   wsq [512]      ||w_m||^2
//   avs [512]      block avg_probs accumulator
//   kls [16]       block KL accumulator (slot 0)
#define SMEM_FLOATS (MDIM * WPAD + TILE * WPAD + MDIM + MDIM + 16)

__global__ void __launch_bounds__(NTHR, 1)
vq_main_kernel(const float* __restrict__ x, const float* __restrict__ u,
               const float* __restrict__ w, float* __restrict__ out)
{
    extern __shared__ float sm[];
    float* w2  = sm;
    float* xs  = w2 + MDIM * WPAD;
    float* wsq = xs + TILE * WPAD;
    float* avs = wsq + MDIM;
    float* kls = avs + MDIM;

    const int tid  = threadIdx.x;
    const int lane = tid & 31;
    const int warp = tid >> 5;

    const int b  = blockIdx.x >> 7;           // 128 tiles per batch (4096/32)
    const int t0 = (blockIdx.x & 127) * TILE;

    // ---- stage weight (coalesced float4 reads) ----
    for (int i = tid; i < MDIM * (DDIM / 4); i += NTHR) {
        const float4 v = ((const float4*)w)[i];
        const int m = i >> 4, d4 = i & 15;
        *(float4*)&w2[m * WPAD + d4 * 4] = v;
    }
    // ---- stage 2*x tile: xs[r][d] = 2 * x[b, d, t0+r] (coalesced over r) ----
    for (int i = tid; i < CDIM * TILE; i += NTHR) {
        const int d = i >> 5, r = i & 31;
        xs[r * WPAD + d] = 2.0f * x[((size_t)b * CDIM + d) * TDIM + t0 + r];
    }
    for (int i = tid; i < MDIM; i += NTHR) avs[i] = 0.f;
    if (tid == 0) kls[0] = 0.f;
    __syncthreads();

    // ---- ||w_m||^2 ----
    for (int m = tid; m < MDIM; m += NTHR) {
        float acc = 0.f;
#pragma unroll
        for (int d = 0; d < DDIM; d += 4) {
            const float4 v = *(const float4*)&w2[m * WPAD + d];
            acc += v.x * v.x + v.y * v.y + v.z * v.z + v.w * v.w;
        }
        wsq[m] = acc;
    }
    __syncthreads();

    // =======================================================================
    // GEMM1: s[r][j] = 2*x_r . w_m - ||w_m||^2,  m = 32*j + lane
    // =======================================================================
    const int r0 = warp * 4;
    float s[4][16];
    {
        float wsql[16];
#pragma unroll
        for (int j = 0; j < 16; j++) wsql[j] = wsq[j * 32 + lane];
#pragma unroll
        for (int r = 0; r < 4; r++)
#pragma unroll
            for (int j = 0; j < 16; j++) s[r][j] = -wsql[j];
    }
#pragma unroll 1
    for (int dc = 0; dc < 8; dc++) {     // 8 floats of D per chunk
        float4 xv[4][2];
#pragma unroll
        for (int r = 0; r < 4; r++) {
            xv[r][0] = *(const float4*)&xs[(r0 + r) * WPAD + dc * 8];
            xv[r][1] = *(const float4*)&xs[(r0 + r) * WPAD + dc * 8 + 4];
        }
#pragma unroll
        for (int j = 0; j < 16; j++) {
            const float4 w0 = *(const float4*)&w2[(j * 32 + lane) * WPAD + dc * 8];
            const float4 w1 = *(const float4*)&w2[(j * 32 + lane) * WPAD + dc * 8 + 4];
#pragma unroll
            for (int r = 0; r < 4; r++) {
                s[r][j] += w0.x * xv[r][0].x + w0.y * xv[r][0].y
                         + w0.z * xv[r][0].z + w0.w * xv[r][0].w
                         + w1.x * xv[r][1].x + w1.y * xv[r][1].y
                         + w1.z * xv[r][1].z + w1.w * xv[r][1].w;
            }
        }
    }

    // =======================================================================
    // Softmaxes: KL (log-softmax of s) + gumbel-softmax samples (overwrite s)
    // =======================================================================
    float avg_acc[16];
#pragma unroll
    for (int j = 0; j < 16; j++) avg_acc[j] = 0.f;
    float kl_acc = 0.f;

#pragma unroll
    for (int r = 0; r < 4; r++) {
        const int t = t0 + r0 + r;

        // log-softmax of s (shift-invariant: ||x||^2 term cancels)
        float mx = -3.4e38f;
#pragma unroll
        for (int j = 0; j < 16; j++) mx = fmaxf(mx, s[r][j]);
        mx = warp_max(mx);
        float se = 0.f;
#pragma unroll
        for (int j = 0; j < 16; j++) se += __expf(s[r][j] - mx);
        se = warp_sum(se);
        const float lse = logf(se);          // precise: 1 per row, feeds KL sum
#pragma unroll
        for (int j = 0; j < 16; j++) {
            const float lp = s[r][j] - mx - lse;
            kl_acc += __expf(lp) * (lp + LN_M);
        }

        // gumbel noise + relaxed softmax at temperature 0.5 (divide -> *2)
        const float* up = u + (size_t)(b * TDIM + t) * MDIM;
        float y[16];
#pragma unroll
        for (int j = 0; j < 16; j++) {
            float uu = up[j * 32 + lane];
            uu = fminf(fmaxf(uu, 1e-9f), 0.99999994f);
            const float inner = log1pf(uu - 1.0f);   // = log(uu), accurate near 1
            const float g = -__logf(-inner);
            y[j] = 2.0f * (s[r][j] + g);
        }
        float my = -3.4e38f;
#pragma unroll
        for (int j = 0; j < 16; j++) my = fmaxf(my, y[j]);
        my = warp_max(my);
        float sy = 0.f;
#pragma unroll
        for (int j = 0; j < 16; j++) { y[j] = __expf(y[j] - my); sy += y[j]; }
        sy = warp_sum(sy);
        const float inv = 1.0f / sy;
#pragma unroll
        for (int j = 0; j < 16; j++) {
            const float p = y[j] * inv;
            s[r][j] = p;                      // samples now live in s
            avg_acc[j] += p;
        }
    }

    // =======================================================================
    // GEMM2: quantized[r][d] = sum_m samples[r][m] * w[m][d]
    // =======================================================================
#pragma unroll 1
    for (int dc8 = 0; dc8 < 8; dc8++) {      // 8 output columns per chunk
        float acc[4][8];
#pragma unroll
        for (int r = 0; r < 4; r++)
#pragma unroll
            for (int i = 0; i < 8; i++) acc[r][i] = 0.f;
#pragma unroll
        for (int j = 0; j < 16; j++) {
            const float4 w0 = *(const float4*)&w2[(j * 32 + lane) * WPAD + dc8 * 8];
            const float4 w1 = *(const float4*)&w2[(j * 32 + lane) * WPAD + dc8 * 8 + 4];
#pragma unroll
            for (int r = 0; r < 4; r++) {
                const float p = s[r][j];
                acc[r][0] += p * w0.x; acc[r][1] += p * w0.y;
                acc[r][2] += p * w0.z; acc[r][3] += p * w0.w;
                acc[r][4] += p * w1.x; acc[r][5] += p * w1.y;
                acc[r][6] += p * w1.z; acc[r][7] += p * w1.w;
            }
        }
        const int c = (lane >> 2) & 7;
#pragma unroll
        for (int r = 0; r < 4; r++) {
            const float tot = reduce8(acc[r], lane);
            if ((lane & 3) == 0) {
                out[(size_t)(b * TDIM + t0 + r0 + r) * DDIM + dc8 * 8 + c] = tot;
            }
        }
    }

    // ---- block-level reductions, then one atomic pass to global scratch ----
#pragma unroll
    for (int j = 0; j < 16; j++) atomicAdd(&avs[j * 32 + lane], avg_acc[j]);
    kl_acc = warp_sum(kl_acc);
    if (lane == 0) atomicAdd(&kls[0], kl_acc);
    __syncthreads();
    for (int i = tid; i < MDIM; i += NTHR) atomicAdd(&g_avg[i], avs[i]);
    if (tid == 0) atomicAdd(&g_kl, kls[0]);
}

__global__ void vq_finalize_kernel(float* __restrict__ out, long long q, int B,
                                   float invN, long long out_size)
{
    __shared__ float red[16];
    const int tid = threadIdx.x;          // 512 threads
    const int lane = tid & 31, warp = tid >> 5;
    const float a = g_avg[tid] * invN;    // avg_probs[m]
    float v = a * logf(a + 1e-10f);
    v = warp_sum(v);
    if (lane == 0) red[warp] = v;
    __syncthreads();
    if (tid == 0) {
        float t = 0.f;
#pragma unroll
        for (int i = 0; i < 16; i++) t += red[i];
        if (q < out_size)     out[q]     = g_kl / (float)B;   // KL (mean over batch)
        if (q + 1 < out_size) out[q + 1] = expf(-t);          // perplexity
    }
}

extern "C" void kernel_launch(void* const* d_in, const int* in_sizes, int n_in,
                              void* d_out, int out_size)
{
    const float* x = (const float*)d_in[0];   // (B, 64, 4096)
    const float* u = (const float*)d_in[1];   // (B, 4096, 512)
    const float* w = (const float*)d_in[2];   // (512, 64)
    float* out = (float*)d_out;

    const int B = in_sizes[0] / (CDIM * TDIM);
    const long long q = (long long)B * TDIM * DDIM;

    static const size_t smem_bytes = SMEM_FLOATS * sizeof(float);
    cudaFuncSetAttribute(vq_main_kernel,
                         cudaFuncAttributeMaxDynamicSharedMemorySize,
                         (int)smem_bytes);

    vq_zero_kernel<<<1, 512>>>();
    vq_main_kernel<<<B * (TDIM / TILE), NTHR, smem_bytes>>>(x, u, w, out);
    vq_finalize_kernel<<<1, 512>>>(out, q, B,
                                   1.0f / (float)((long long)B * TDIM),
                                   (long long)out_size);
}